// round 6
// baseline (speedup 1.0000x reference)
#include <cuda_runtime.h>

#define BS    2048
#define NINP  512
#define NHID  512
#define TT    8
#define MM    32
#define NTOT  32768
#define GI_COLS 768
#define NPAIR (NTOT/2)   // 16384

typedef unsigned long long u64;

// device scratch
__device__ float g_gi[BS * GI_COLS];       // [2048][768], 6 MB
__device__ float g_hn[TT * NTOT * MM];     // hnext [t][n][m], 32 MB
__device__ float g_lg[NTOT * TT];          // logits [n][t], 1 MB

// ---- packed f32x2 helpers (Blackwell FFMA2) --------------------------------
__device__ __forceinline__ void fma2(u64& acc, u64 a, u64 b) {
    asm("fma.rn.f32x2 %0, %1, %2, %0;" : "+l"(acc) : "l"(a), "l"(b));
}
__device__ __forceinline__ u64 pk(float lo, float hi) {
    u64 r; asm("mov.b64 %0, {%1, %2};" : "=l"(r) : "f"(lo), "f"(hi)); return r;
}
__device__ __forceinline__ void unpk(float& lo, float& hi, u64 v) {
    asm("mov.b64 {%0, %1}, %2;" : "=f"(lo), "=f"(hi) : "l"(v));
}
__device__ __forceinline__ float hadd(u64 v) {
    float a, b; unpk(a, b, v); return a + b;
}

// ---------------------------------------------------------------------------
// Kernel 1: gi = x @ W_ih^T + b_ih.  C[2048,768] = A[2048,512]*B[768,512]^T.
// 64x64 tile, 128 threads, 8x4 per thread, FFMA2 paired over k.
// ---------------------------------------------------------------------------
#define GT 128
__global__ void __launch_bounds__(GT) gemm_gi_kernel(
    const float* __restrict__ A,
    const float* __restrict__ B,
    const float* __restrict__ bias)
{
    __shared__ float As[64 * 36];   // [m][k] natural, stride 36 (144B)
    __shared__ float Bs[64 * 36];   // [n][k]

    const int tid = threadIdx.x;
    const int tx  = tid & 15;       // 4 cols: n0+tx*4..
    const int ty  = tid >> 4;       // 8 rows: m0+ty*8..
    const int m0  = blockIdx.y * 64;
    const int n0  = blockIdx.x * 64;

    u64 acc[8][4];
#pragma unroll
    for (int i = 0; i < 8; i++)
#pragma unroll
        for (int j = 0; j < 4; j++) acc[i][j] = 0ull;   // (0.f, 0.f)

    for (int k0 = 0; k0 < NINP; k0 += 32) {
#pragma unroll
        for (int it = 0; it < 4; it++) {
            int idx = tid + GT * it;          // 0..511
            int row = idx >> 3;               // 0..63
            int c4  = idx & 7;                // float4 chunk of 32 k
            *(float4*)&As[row * 36 + c4 * 4] =
                *(const float4*)&A[(m0 + row) * NINP + k0 + c4 * 4];
            *(float4*)&Bs[row * 36 + c4 * 4] =
                *(const float4*)&B[(n0 + row) * NINP + k0 + c4 * 4];
        }
        __syncthreads();
#pragma unroll
        for (int kc = 0; kc < 8; kc++) {      // 4 k per step
            ulonglong2 b2[4];
#pragma unroll
            for (int j = 0; j < 4; j++)
                b2[j] = *(const ulonglong2*)&Bs[(tx * 4 + j) * 36 + kc * 4];
#pragma unroll
            for (int i = 0; i < 8; i++) {
                ulonglong2 a2 = *(const ulonglong2*)&As[(ty * 8 + i) * 36 + kc * 4];
#pragma unroll
                for (int j = 0; j < 4; j++) {
                    fma2(acc[i][j], a2.x, b2[j].x);
                    fma2(acc[i][j], a2.y, b2[j].y);
                }
            }
        }
        __syncthreads();
    }

    float4 bj = *(const float4*)&bias[n0 + tx * 4];
#pragma unroll
    for (int i = 0; i < 8; i++) {
        float4 v;
        v.x = hadd(acc[i][0]) + bj.x;
        v.y = hadd(acc[i][1]) + bj.y;
        v.z = hadd(acc[i][2]) + bj.z;
        v.w = hadd(acc[i][3]) + bj.w;
        *(float4*)&g_gi[(m0 + ty * 8 + i) * GI_COLS + n0 + tx * 4] = v;
    }
}

// ---------------------------------------------------------------------------
// Kernel A: gates + hnext + logit.  blockIdx.y = template t.
// Thread handles the pair (n1 = b*16+k, n2 = n1+8): shared b -> shared gi,
// shared weight LDS. 192 thr, 2 blocks/SM (170-reg cap, no spills).
// ---------------------------------------------------------------------------
#define PT 192
__global__ void __launch_bounds__(PT, 2) gates_kernel(
    const float* __restrict__ h,
    const float* __restrict__ W_hh,
    const float* __restrict__ b_hh,
    const float* __restrict__ w_read,
    const float* __restrict__ w_write)
{
    __shared__ float Wg[96 * 32];    // this template's gate weights  12 KB
    __shared__ float Ww[32 * 16];    // w_write[t]
    __shared__ float Wr[32 * 16];    // w_read
    __shared__ float bs[96];         // b_hh[t]

    const int tid = threadIdx.x;
    const int t   = blockIdx.y;

    {   // stage
        const float4* s1 = (const float4*)(W_hh + t * 96 * 32);
        float4* d1 = (float4*)Wg;
        for (int i = tid; i < 768; i += PT) d1[i] = s1[i];
        if (tid < 128) ((float4*)Ww)[tid] = ((const float4*)(w_write + t * 512))[tid];
        if (tid < 128) ((float4*)Wr)[tid] = ((const float4*)w_read)[tid];
        if (tid < 24)  ((float4*)bs)[tid] = ((const float4*)(b_hh + t * 96))[tid];
    }
    __syncthreads();

    const int p = blockIdx.x * PT + tid;
    if (p >= NPAIR) return;            // no later syncs
    const int b  = p >> 3;
    const int n1 = b * 16 + (p & 7);
    const int n2 = n1 + 8;

    // h state, packed (m-pairs)
    u64 hA[16], hB[16];
    {
        const ulonglong2* h1 = (const ulonglong2*)(h + n1 * MM);
        const ulonglong2* h2 = (const ulonglong2*)(h + n2 * MM);
#pragma unroll
        for (int q = 0; q < 8; q++) {
            ulonglong2 v = h1[q]; hA[2*q] = v.x; hA[2*q+1] = v.y;
            ulonglong2 w = h2[q]; hB[2*q] = w.x; hB[2*q+1] = w.y;
        }
    }

    // h_read, packed over f-pairs: hr[f] = sum_m h[m]*w_read[m][f]
    u64 hrA[8], hrB[8];
#pragma unroll
    for (int i = 0; i < 8; i++) { hrA[i] = 0ull; hrB[i] = 0ull; }
#pragma unroll 4
    for (int m = 0; m < 32; m++) {
        const ulonglong2* w = (const ulonglong2*)(Wr + m * 16);
        ulonglong2 w0 = w[0], w1 = w[1], w2 = w[2], w3 = w[3];
        float lo, hi;
        unpk(lo, hi, hA[m >> 1]); float ha = (m & 1) ? hi : lo;
        unpk(lo, hi, hB[m >> 1]); float hb = (m & 1) ? hi : lo;
        u64 dA = pk(ha, ha), dB = pk(hb, hb);
        fma2(hrA[0], dA, w0.x); fma2(hrA[1], dA, w0.y);
        fma2(hrA[2], dA, w1.x); fma2(hrA[3], dA, w1.y);
        fma2(hrA[4], dA, w2.x); fma2(hrA[5], dA, w2.y);
        fma2(hrA[6], dA, w3.x); fma2(hrA[7], dA, w3.y);
        fma2(hrB[0], dB, w0.x); fma2(hrB[1], dB, w0.y);
        fma2(hrB[2], dB, w1.x); fma2(hrB[3], dB, w1.y);
        fma2(hrB[4], dB, w2.x); fma2(hrB[5], dB, w2.y);
        fma2(hrB[6], dB, w3.x); fma2(hrB[7], dB, w3.y);
    }

    const float* gib = g_gi + b * GI_COLS + t * 96;
    float* ho1 = g_hn + (t * NTOT + n1) * MM;
    float* ho2 = g_hn + (t * NTOT + n2) * MM;
    float lg1 = 0.f, lg2 = 0.f;

#pragma unroll 1
    for (int l4 = 0; l4 < 8; l4++) {
        float Ga[4], Gb[4], Gc[4];
        *(float4*)Ga = *(const float4*)(gib + 4*l4);
        *(float4*)Gb = *(const float4*)(gib + 32 + 4*l4);
        *(float4*)Gc = *(const float4*)(gib + 64 + 4*l4);
        float o1[4], o2[4];
#pragma unroll
        for (int li = 0; li < 4; li++) {
            const int l = 4*l4 + li;
            const ulonglong2* wr = (const ulonglong2*)(Wg + l * 32);
            const ulonglong2* wz = (const ulonglong2*)(Wg + (32 + l) * 32);
            const ulonglong2* wn = (const ulonglong2*)(Wg + (64 + l) * 32);
            u64 aR1 = pk(bs[l],      0.f), aR2 = aR1;
            u64 aZ1 = pk(bs[32 + l], 0.f), aZ2 = aZ1;
            u64 aN1 = pk(bs[64 + l], 0.f), aN2 = aN1;
#pragma unroll
            for (int q = 0; q < 8; q++) {
                ulonglong2 wa = wr[q];
                fma2(aR1, wa.x, hA[2*q]); fma2(aR1, wa.y, hA[2*q+1]);
                fma2(aR2, wa.x, hB[2*q]); fma2(aR2, wa.y, hB[2*q+1]);
            }
#pragma unroll
            for (int q = 0; q < 8; q++) {
                ulonglong2 wb = wz[q];
                fma2(aZ1, wb.x, hA[2*q]); fma2(aZ1, wb.y, hA[2*q+1]);
                fma2(aZ2, wb.x, hB[2*q]); fma2(aZ2, wb.y, hB[2*q+1]);
            }
#pragma unroll
            for (int q = 0; q < 8; q++) {
                ulonglong2 wc = wn[q];
                fma2(aN1, wc.x, hA[2*q]); fma2(aN1, wc.y, hA[2*q+1]);
                fma2(aN2, wc.x, hB[2*q]); fma2(aN2, wc.y, hB[2*q+1]);
            }
            // av = w_write[t][l] . h_read (packed over f-pairs)
            const ulonglong2* ww = (const ulonglong2*)(Ww + l * 16);
            ulonglong2 w0 = ww[0], w1 = ww[1], w2 = ww[2], w3 = ww[3];
            u64 aA1 = 0ull, aA2 = 0ull;
            fma2(aA1, w0.x, hrA[0]); fma2(aA1, w0.y, hrA[1]);
            fma2(aA1, w1.x, hrA[2]); fma2(aA1, w1.y, hrA[3]);
            fma2(aA1, w2.x, hrA[4]); fma2(aA1, w2.y, hrA[5]);
            fma2(aA1, w3.x, hrA[6]); fma2(aA1, w3.y, hrA[7]);
            fma2(aA2, w0.x, hrB[0]); fma2(aA2, w0.y, hrB[1]);
            fma2(aA2, w1.x, hrB[2]); fma2(aA2, w1.y, hrB[3]);
            fma2(aA2, w2.x, hrB[4]); fma2(aA2, w2.y, hrB[5]);
            fma2(aA2, w3.x, hrB[6]); fma2(aA2, w3.y, hrB[7]);

            {
                float ar = hadd(aR1), az = hadd(aZ1), an = hadd(aN1), av = hadd(aA1);
                float lo, hi; unpk(lo, hi, hA[l >> 1]); float hl = (l & 1) ? hi : lo;
                float r  = __fdividef(1.f, 1.f + __expf(-(Ga[li] + ar)));
                float z  = __fdividef(1.f, 1.f + __expf(-(Gb[li] + az)));
                float xn = Gc[li] + r * an;
                float e2 = __expf(-2.f * xn);
                float nn = __fdividef(1.f - e2, 1.f + e2);
                float hn = (1.f - z) * nn + z * hl;
                o1[li] = hn;
                lg1 = fmaf(hn, av, lg1);
            }
            {
                float ar = hadd(aR2), az = hadd(aZ2), an = hadd(aN2), av = hadd(aA2);
                float lo, hi; unpk(lo, hi, hB[l >> 1]); float hl = (l & 1) ? hi : lo;
                float r  = __fdividef(1.f, 1.f + __expf(-(Ga[li] + ar)));
                float z  = __fdividef(1.f, 1.f + __expf(-(Gb[li] + az)));
                float xn = Gc[li] + r * an;
                float e2 = __expf(-2.f * xn);
                float nn = __fdividef(1.f - e2, 1.f + e2);
                float hn = (1.f - z) * nn + z * hl;
                o2[li] = hn;
                lg2 = fmaf(hn, av, lg2);
            }
        }
        *(float4*)(ho1 + 4*l4) = *(float4*)o1;
        *(float4*)(ho2 + 4*l4) = *(float4*)o2;
    }
    g_lg[n1 * TT + t] = lg1;
    g_lg[n2 * TT + t] = lg2;
}

// ---------------------------------------------------------------------------
// Kernel B: gumbel softmax + hard select + gather + outputs
// ---------------------------------------------------------------------------
__global__ void __launch_bounds__(256) select_kernel(
    const float* __restrict__ gum,
    float* __restrict__ out)
{
    const int n = blockIdx.x * 256 + threadIdx.x;

    float s[8];
    {
        const float4* lp = (const float4*)(g_lg + n * TT);
        const float4* gp = (const float4*)(gum + n * TT);
        float4 l0 = lp[0], l1 = lp[1], g0 = gp[0], g1 = gp[1];
        s[0] = (l0.x + g0.x) * 2.f; s[1] = (l0.y + g0.y) * 2.f;
        s[2] = (l0.z + g0.z) * 2.f; s[3] = (l0.w + g0.w) * 2.f;
        s[4] = (l1.x + g1.x) * 2.f; s[5] = (l1.y + g1.y) * 2.f;
        s[6] = (l1.z + g1.z) * 2.f; s[7] = (l1.w + g1.w) * 2.f;
    }
    float smax = s[0];
    int amax = 0;
#pragma unroll
    for (int t = 1; t < 8; t++)
        if (s[t] > smax) { smax = s[t]; amax = t; }
    float sum = 0.f;
#pragma unroll
    for (int t = 0; t < 8; t++) sum += __expf(s[t] - smax);

    float p = __fdividef(1.f, sum);         // softmax at argmax
    float attv = (1.f + p) - p;             // straight-through residual, exact

    const float4* hp = (const float4*)(g_hn + (amax * NTOT + n) * MM);
    float4* ho = (float4*)(out + n * MM);
#pragma unroll
    for (int i = 0; i < 8; i++) {
        float4 v = hp[i];
        v.x *= attv; v.y *= attv; v.z *= attv; v.w *= attv;
        ho[i] = v;
    }
    float* ao = out + BS * NHID + n * TT;
#pragma unroll
    for (int t = 0; t < 8; t++) ao[t] = (t == amax) ? attv : 0.f;
}

// ---------------------------------------------------------------------------
extern "C" void kernel_launch(void* const* d_in, const int* in_sizes, int n_in,
                              void* d_out, int out_size)
{
    const float* x       = (const float*)d_in[0];
    const float* h       = (const float*)d_in[1];
    const float* W_ih    = (const float*)d_in[2];
    const float* W_hh    = (const float*)d_in[3];
    const float* b_ih    = (const float*)d_in[4];
    const float* b_hh    = (const float*)d_in[5];
    const float* w_read  = (const float*)d_in[6];
    const float* w_write = (const float*)d_in[7];
    const float* gum     = (const float*)d_in[8];
    float* out = (float*)d_out;

    dim3 g1(GI_COLS / 64, BS / 64);                   // (12, 32)
    gemm_gi_kernel<<<g1, GT>>>(x, W_ih, b_ih);

    dim3 g2((NPAIR + PT - 1) / PT, TT);               // (86, 8)
    gates_kernel<<<g2, PT>>>(h, W_hh, b_hh, w_read, w_write);

    select_kernel<<<NTOT / 256, 256>>>(gum, out);
}

// round 7
// speedup vs baseline: 1.0581x; 1.0581x over previous
#include <cuda_runtime.h>

#define BS    2048
#define NINP  512
#define NHID  512
#define TT    8
#define MM    32
#define NTOT  32768
#define GI_COLS 768
#define NPAIR (NTOT/2)   // 16384

typedef unsigned long long u64;

// device scratch
__device__ float g_gi[BS * GI_COLS];       // [2048][768], 6 MB
__device__ float g_hn[TT * NTOT * MM];     // hnext [t][n][m], 32 MB
__device__ float g_lg[NTOT * TT];          // logits [n][t], 1 MB

// ---- packed f32x2 helpers (used by gates kernel) ---------------------------
__device__ __forceinline__ void fma2(u64& acc, u64 a, u64 b) {
    asm("fma.rn.f32x2 %0, %1, %2, %0;" : "+l"(acc) : "l"(a), "l"(b));
}
__device__ __forceinline__ u64 pk(float lo, float hi) {
    u64 r; asm("mov.b64 %0, {%1, %2};" : "=l"(r) : "f"(lo), "f"(hi)); return r;
}
__device__ __forceinline__ void unpk(float& lo, float& hi, u64 v) {
    asm("mov.b64 {%0, %1}, %2;" : "=f"(lo), "=f"(hi) : "l"(v));
}
__device__ __forceinline__ float hadd(u64 v) {
    float a, b; unpk(a, b, v); return a + b;
}

// ---------------------------------------------------------------------------
// Kernel 1: gi = x @ W_ih^T + b_ih.  C[2048,768] = A[2048,512]*B[768,512]^T.
// 32x64 tile, 128 threads, 4x4/thread, scalar FFMA, double-buffered smem.
// Grid 768 -> ~5.2 blocks/SM.
// ---------------------------------------------------------------------------
#define GT 128
#define SA 36     // As row stride ([k][m]), 144B (16B-aligned)
#define SB 68     // Bs row stride ([k][n]), 272B (16B-aligned)

__global__ void __launch_bounds__(GT) gemm_gi_kernel(
    const float* __restrict__ A,
    const float* __restrict__ B,
    const float* __restrict__ bias)
{
    __shared__ float As[2][32 * SA];   // [k][m]
    __shared__ float Bs[2][32 * SB];   // [k][n]

    const int tid = threadIdx.x;
    const int tx  = tid & 15;          // n: 4 cols at n0+tx*4
    const int ty  = tid >> 4;          // m: 4 rows at m0+ty*4
    const int m0  = blockIdx.y * 32;
    const int n0  = blockIdx.x * 64;

    // staging coords (A: 256 float4 over 2 iters; B: 512 float4 over 4 iters)
    const int ar0 = tid >> 3;          // A row within 32 (it adds +16)
    const int ac  = (tid & 7) * 4;     // k offset
    const int br0 = tid >> 3;          // B row within 64 (it adds +16)

    float4 ra[2], rb[4];

    #define LDG_CHUNK(k0)                                                    \
        {                                                                    \
            ra[0] = *(const float4*)&A[(m0 + ar0)      * NINP + (k0) + ac];  \
            ra[1] = *(const float4*)&A[(m0 + ar0 + 16) * NINP + (k0) + ac];  \
            rb[0] = *(const float4*)&B[(n0 + br0)      * NINP + (k0) + ac];  \
            rb[1] = *(const float4*)&B[(n0 + br0 + 16) * NINP + (k0) + ac];  \
            rb[2] = *(const float4*)&B[(n0 + br0 + 32) * NINP + (k0) + ac];  \
            rb[3] = *(const float4*)&B[(n0 + br0 + 48) * NINP + (k0) + ac];  \
        }

    #define STS_CHUNK(buf)                                                   \
        {                                                                    \
            const float* va = (const float*)ra;                              \
            const float* vb = (const float*)rb;                              \
            _Pragma("unroll")                                                \
            for (int w = 0; w < 4; w++) {                                    \
                As[buf][(ac + w) * SA + ar0]      = va[w];                    \
                As[buf][(ac + w) * SA + ar0 + 16] = va[4 + w];                \
                Bs[buf][(ac + w) * SB + br0]      = vb[w];                    \
                Bs[buf][(ac + w) * SB + br0 + 16] = vb[4 + w];                \
                Bs[buf][(ac + w) * SB + br0 + 32] = vb[8 + w];                \
                Bs[buf][(ac + w) * SB + br0 + 48] = vb[12 + w];               \
            }                                                                \
        }

    float acc[4][4];
#pragma unroll
    for (int i = 0; i < 4; i++)
#pragma unroll
        for (int j = 0; j < 4; j++) acc[i][j] = 0.f;

    // prologue: stage chunk 0, prefetch chunk 1
    LDG_CHUNK(0);
    STS_CHUNK(0);
    LDG_CHUNK(32);
    __syncthreads();

#pragma unroll 1
    for (int c = 0; c < 16; c++) {
        const int buf = c & 1;
        if (c < 15) {
            STS_CHUNK(buf ^ 1);            // stage chunk c+1 (other buffer)
        }
        if (c < 14) {
            LDG_CHUNK((c + 2) * 32);       // prefetch chunk c+2
        }
#pragma unroll
        for (int k = 0; k < 32; k++) {
            float4 a4 = *(const float4*)&As[buf][k * SA + ty * 4];
            float4 b4 = *(const float4*)&Bs[buf][k * SB + tx * 4];
            float a[4] = {a4.x, a4.y, a4.z, a4.w};
            float b[4] = {b4.x, b4.y, b4.z, b4.w};
#pragma unroll
            for (int i = 0; i < 4; i++)
#pragma unroll
                for (int j = 0; j < 4; j++)
                    acc[i][j] = fmaf(a[i], b[j], acc[i][j]);
        }
        __syncthreads();
    }

    float4 bj = *(const float4*)&bias[n0 + tx * 4];
#pragma unroll
    for (int i = 0; i < 4; i++) {
        float4 v;
        v.x = acc[i][0] + bj.x;
        v.y = acc[i][1] + bj.y;
        v.z = acc[i][2] + bj.z;
        v.w = acc[i][3] + bj.w;
        *(float4*)&g_gi[(m0 + ty * 4 + i) * GI_COLS + n0 + tx * 4] = v;
    }
    #undef LDG_CHUNK
    #undef STS_CHUNK
}

// ---------------------------------------------------------------------------
// Kernel A: gates + hnext + logit.  blockIdx.y = template t.
// Thread handles the pair (n1 = b*16+k, n2 = n1+8): shared b -> shared gi,
// shared weight LDS. 192 thr, 2 blocks/SM (170-reg cap, no spills).
// ---------------------------------------------------------------------------
#define PT 192
__global__ void __launch_bounds__(PT, 2) gates_kernel(
    const float* __restrict__ h,
    const float* __restrict__ W_hh,
    const float* __restrict__ b_hh,
    const float* __restrict__ w_read,
    const float* __restrict__ w_write)
{
    __shared__ float Wg[96 * 32];    // this template's gate weights  12 KB
    __shared__ float Ww[32 * 16];    // w_write[t]
    __shared__ float Wr[32 * 16];    // w_read
    __shared__ float bs[96];         // b_hh[t]

    const int tid = threadIdx.x;
    const int t   = blockIdx.y;

    {   // stage
        const float4* s1 = (const float4*)(W_hh + t * 96 * 32);
        float4* d1 = (float4*)Wg;
        for (int i = tid; i < 768; i += PT) d1[i] = s1[i];
        if (tid < 128) ((float4*)Ww)[tid] = ((const float4*)(w_write + t * 512))[tid];
        if (tid < 128) ((float4*)Wr)[tid] = ((const float4*)w_read)[tid];
        if (tid < 24)  ((float4*)bs)[tid] = ((const float4*)(b_hh + t * 96))[tid];
    }
    __syncthreads();

    const int p = blockIdx.x * PT + tid;
    if (p >= NPAIR) return;            // no later syncs
    const int b  = p >> 3;
    const int n1 = b * 16 + (p & 7);
    const int n2 = n1 + 8;

    // h state, packed (m-pairs)
    u64 hA[16], hB[16];
    {
        const ulonglong2* h1 = (const ulonglong2*)(h + n1 * MM);
        const ulonglong2* h2 = (const ulonglong2*)(h + n2 * MM);
#pragma unroll
        for (int q = 0; q < 8; q++) {
            ulonglong2 v = h1[q]; hA[2*q] = v.x; hA[2*q+1] = v.y;
            ulonglong2 w = h2[q]; hB[2*q] = w.x; hB[2*q+1] = w.y;
        }
    }

    // h_read, packed over f-pairs: hr[f] = sum_m h[m]*w_read[m][f]
    u64 hrA[8], hrB[8];
#pragma unroll
    for (int i = 0; i < 8; i++) { hrA[i] = 0ull; hrB[i] = 0ull; }
#pragma unroll 4
    for (int m = 0; m < 32; m++) {
        const ulonglong2* w = (const ulonglong2*)(Wr + m * 16);
        ulonglong2 w0 = w[0], w1 = w[1], w2 = w[2], w3 = w[3];
        float lo, hi;
        unpk(lo, hi, hA[m >> 1]); float ha = (m & 1) ? hi : lo;
        unpk(lo, hi, hB[m >> 1]); float hb = (m & 1) ? hi : lo;
        u64 dA = pk(ha, ha), dB = pk(hb, hb);
        fma2(hrA[0], dA, w0.x); fma2(hrA[1], dA, w0.y);
        fma2(hrA[2], dA, w1.x); fma2(hrA[3], dA, w1.y);
        fma2(hrA[4], dA, w2.x); fma2(hrA[5], dA, w2.y);
        fma2(hrA[6], dA, w3.x); fma2(hrA[7], dA, w3.y);
        fma2(hrB[0], dB, w0.x); fma2(hrB[1], dB, w0.y);
        fma2(hrB[2], dB, w1.x); fma2(hrB[3], dB, w1.y);
        fma2(hrB[4], dB, w2.x); fma2(hrB[5], dB, w2.y);
        fma2(hrB[6], dB, w3.x); fma2(hrB[7], dB, w3.y);
    }

    const float* gib = g_gi + b * GI_COLS + t * 96;
    float* ho1 = g_hn + (t * NTOT + n1) * MM;
    float* ho2 = g_hn + (t * NTOT + n2) * MM;
    float lg1 = 0.f, lg2 = 0.f;

#pragma unroll 1
    for (int l4 = 0; l4 < 8; l4++) {
        float Ga[4], Gb[4], Gc[4];
        *(float4*)Ga = *(const float4*)(gib + 4*l4);
        *(float4*)Gb = *(const float4*)(gib + 32 + 4*l4);
        *(float4*)Gc = *(const float4*)(gib + 64 + 4*l4);
        float o1[4], o2[4];
#pragma unroll
        for (int li = 0; li < 4; li++) {
            const int l = 4*l4 + li;
            const ulonglong2* wr = (const ulonglong2*)(Wg + l * 32);
            const ulonglong2* wz = (const ulonglong2*)(Wg + (32 + l) * 32);
            const ulonglong2* wn = (const ulonglong2*)(Wg + (64 + l) * 32);
            u64 aR1 = pk(bs[l],      0.f), aR2 = aR1;
            u64 aZ1 = pk(bs[32 + l], 0.f), aZ2 = aZ1;
            u64 aN1 = pk(bs[64 + l], 0.f), aN2 = aN1;
#pragma unroll
            for (int q = 0; q < 8; q++) {
                ulonglong2 wa = wr[q];
                fma2(aR1, wa.x, hA[2*q]); fma2(aR1, wa.y, hA[2*q+1]);
                fma2(aR2, wa.x, hB[2*q]); fma2(aR2, wa.y, hB[2*q+1]);
            }
#pragma unroll
            for (int q = 0; q < 8; q++) {
                ulonglong2 wb = wz[q];
                fma2(aZ1, wb.x, hA[2*q]); fma2(aZ1, wb.y, hA[2*q+1]);
                fma2(aZ2, wb.x, hB[2*q]); fma2(aZ2, wb.y, hB[2*q+1]);
            }
#pragma unroll
            for (int q = 0; q < 8; q++) {
                ulonglong2 wc = wn[q];
                fma2(aN1, wc.x, hA[2*q]); fma2(aN1, wc.y, hA[2*q+1]);
                fma2(aN2, wc.x, hB[2*q]); fma2(aN2, wc.y, hB[2*q+1]);
            }
            // av = w_write[t][l] . h_read (packed over f-pairs)
            const ulonglong2* ww = (const ulonglong2*)(Ww + l * 16);
            ulonglong2 w0 = ww[0], w1 = ww[1], w2 = ww[2], w3 = ww[3];
            u64 aA1 = 0ull, aA2 = 0ull;
            fma2(aA1, w0.x, hrA[0]); fma2(aA1, w0.y, hrA[1]);
            fma2(aA1, w1.x, hrA[2]); fma2(aA1, w1.y, hrA[3]);
            fma2(aA1, w2.x, hrA[4]); fma2(aA1, w2.y, hrA[5]);
            fma2(aA1, w3.x, hrA[6]); fma2(aA1, w3.y, hrA[7]);
            fma2(aA2, w0.x, hrB[0]); fma2(aA2, w0.y, hrB[1]);
            fma2(aA2, w1.x, hrB[2]); fma2(aA2, w1.y, hrB[3]);
            fma2(aA2, w2.x, hrB[4]); fma2(aA2, w2.y, hrB[5]);
            fma2(aA2, w3.x, hrB[6]); fma2(aA2, w3.y, hrB[7]);

            {
                float ar = hadd(aR1), az = hadd(aZ1), an = hadd(aN1), av = hadd(aA1);
                float lo, hi; unpk(lo, hi, hA[l >> 1]); float hl = (l & 1) ? hi : lo;
                float r  = __fdividef(1.f, 1.f + __expf(-(Ga[li] + ar)));
                float z  = __fdividef(1.f, 1.f + __expf(-(Gb[li] + az)));
                float xn = Gc[li] + r * an;
                float e2 = __expf(-2.f * xn);
                float nn = __fdividef(1.f - e2, 1.f + e2);
                float hn = (1.f - z) * nn + z * hl;
                o1[li] = hn;
                lg1 = fmaf(hn, av, lg1);
            }
            {
                float ar = hadd(aR2), az = hadd(aZ2), an = hadd(aN2), av = hadd(aA2);
                float lo, hi; unpk(lo, hi, hB[l >> 1]); float hl = (l & 1) ? hi : lo;
                float r  = __fdividef(1.f, 1.f + __expf(-(Ga[li] + ar)));
                float z  = __fdividef(1.f, 1.f + __expf(-(Gb[li] + az)));
                float xn = Gc[li] + r * an;
                float e2 = __expf(-2.f * xn);
                float nn = __fdividef(1.f - e2, 1.f + e2);
                float hn = (1.f - z) * nn + z * hl;
                o2[li] = hn;
                lg2 = fmaf(hn, av, lg2);
            }
        }
        *(float4*)(ho1 + 4*l4) = *(float4*)o1;
        *(float4*)(ho2 + 4*l4) = *(float4*)o2;
    }
    g_lg[n1 * TT + t] = lg1;
    g_lg[n2 * TT + t] = lg2;
}

// ---------------------------------------------------------------------------
// Kernel B: gumbel softmax + hard select + gather + outputs
// ---------------------------------------------------------------------------
__global__ void __launch_bounds__(256) select_kernel(
    const float* __restrict__ gum,
    float* __restrict__ out)
{
    const int n = blockIdx.x * 256 + threadIdx.x;

    float s[8];
    {
        const float4* lp = (const float4*)(g_lg + n * TT);
        const float4* gp = (const float4*)(gum + n * TT);
        float4 l0 = lp[0], l1 = lp[1], g0 = gp[0], g1 = gp[1];
        s[0] = (l0.x + g0.x) * 2.f; s[1] = (l0.y + g0.y) * 2.f;
        s[2] = (l0.z + g0.z) * 2.f; s[3] = (l0.w + g0.w) * 2.f;
        s[4] = (l1.x + g1.x) * 2.f; s[5] = (l1.y + g1.y) * 2.f;
        s[6] = (l1.z + g1.z) * 2.f; s[7] = (l1.w + g1.w) * 2.f;
    }
    float smax = s[0];
    int amax = 0;
#pragma unroll
    for (int t = 1; t < 8; t++)
        if (s[t] > smax) { smax = s[t]; amax = t; }
    float sum = 0.f;
#pragma unroll
    for (int t = 0; t < 8; t++) sum += __expf(s[t] - smax);

    float p = __fdividef(1.f, sum);         // softmax at argmax
    float attv = (1.f + p) - p;             // straight-through residual, exact

    const float4* hp = (const float4*)(g_hn + (amax * NTOT + n) * MM);
    float4* ho = (float4*)(out + n * MM);
#pragma unroll
    for (int i = 0; i < 8; i++) {
        float4 v = hp[i];
        v.x *= attv; v.y *= attv; v.z *= attv; v.w *= attv;
        ho[i] = v;
    }
    float* ao = out + BS * NHID + n * TT;
#pragma unroll
    for (int t = 0; t < 8; t++) ao[t] = (t == amax) ? attv : 0.f;
}

// ---------------------------------------------------------------------------
extern "C" void kernel_launch(void* const* d_in, const int* in_sizes, int n_in,
                              void* d_out, int out_size)
{
    const float* x       = (const float*)d_in[0];
    const float* h       = (const float*)d_in[1];
    const float* W_ih    = (const float*)d_in[2];
    const float* W_hh    = (const float*)d_in[3];
    const float* b_ih    = (const float*)d_in[4];
    const float* b_hh    = (const float*)d_in[5];
    const float* w_read  = (const float*)d_in[6];
    const float* w_write = (const float*)d_in[7];
    const float* gum     = (const float*)d_in[8];
    float* out = (float*)d_out;

    dim3 g1(GI_COLS / 64, BS / 32);                   // (12, 64) = 768 blocks
    gemm_gi_kernel<<<g1, GT>>>(x, W_ih, b_ih);

    dim3 g2((NPAIR + PT - 1) / PT, TT);               // (86, 8)
    gates_kernel<<<g2, PT>>>(h, W_hh, b_hh, w_read, w_write);

    select_kernel<<<NTOT / 256, 256>>>(gum, out);
}